// round 9
// baseline (speedup 1.0000x reference)
#include <cuda_runtime.h>
#include <cuda_fp16.h>
#include <math.h>
#include <stdint.h>

#define HDIM 512
#define NPT  4095
#define NB   8
#define NTOT (NPT*NB)

typedef __half hlf;

// ---------------- device scratch ----------------
__device__ float g_h [(size_t)NTOT*HDIM];
__device__ float g_hd[(size_t)NTOT*HDIM];
__device__ float g_z [(size_t)16384*HDIM];
__device__ hlf g_xs [(size_t)NTOT*HDIM];
__device__ hlf g_hsp[(size_t)NTOT*HDIM];
__device__ hlf g_hdp[(size_t)NTOT*HDIM];
__device__ hlf g_V  [(size_t)16384*HDIM];
__device__ hlf g_W  [(size_t)7*512*1024];

__device__ __forceinline__ float sigf(float x){ return 1.f/(1.f+expf(-x)); }
__device__ __forceinline__ uint32_t pack2f(float a, float b){
    __half2 p = __floats2half2_rn(a,b);
    return *reinterpret_cast<uint32_t*>(&p);
}
__device__ __forceinline__ void st_h2(hlf* p, float a, float b){
    *reinterpret_cast<__half2*>(p) = __floats2half2_rn(a,b);
}
__device__ __forceinline__ void st_h4(hlf* p, float a, float b, float c, float d){
    uint2 v; v.x = pack2f(a,b); v.y = pack2f(c,d);
    *reinterpret_cast<uint2*>(p) = v;
}

// ---------------- setup kernels ----------------
__global__ void split_w(const float* Wz,const float* Uz,const float* Wr,const float* Ur,
                        const float* Wh,const float* Uh,const float* Wzd,const float* Uzd,
                        const float* Wrd,const float* Urd,const float* Whd,const float* Uhd,
                        const float* W1,const float* W2)
{
    int slot = blockIdx.y;
    const float* Wp; const float* Up;
    switch(slot){
        case 0: Wp=Wz;  Up=Uz;  break;
        case 1: Wp=Wr;  Up=Ur;  break;
        case 2: Wp=Wh;  Up=Uh;  break;
        case 3: Wp=Wzd; Up=Uzd; break;
        case 4: Wp=Wrd; Up=Urd; break;
        case 5: Wp=Whd; Up=Uhd; break;
        default:Wp=W1;  Up=W2;  break;
    }
    int idx = blockIdx.x*256 + threadIdx.x;
    int n = idx >> 10, k = idx & 1023;
    float x = (k < 512) ? Wp[n*512 + k] : Up[n*512 + (k-512)];
    g_W[(size_t)slot*524288 + idx] = __float2half_rn(x);
}

__global__ void split_feat(const float* __restrict__ src)
{
    size_t idx = (size_t)blockIdx.x*256 + threadIdx.x;
    g_xs[idx] = __float2half_rn(src[idx]);
}

__global__ void root_copy()
{
    int idx = blockIdx.x*256 + threadIdx.x;
    if (idx >= NB*HDIM) return;
    int tree = idx >> 9, k = idx & 511;
    size_t o = (size_t)(tree*NPT + NPT-1)*HDIM + k;
    float v = g_h[o];
    g_hd[o] = v;
    g_hdp[o] = __float2half_rn(v);
}

// ---------------- PTX helpers ----------------
#define MMA_F16(d, a, b) asm volatile( \
  "mma.sync.aligned.m16n8k16.row.col.f32.f16.f16.f32 " \
  "{%0,%1,%2,%3}, {%4,%5,%6,%7}, {%8,%9}, {%0,%1,%2,%3};\n" \
  : "+f"(d[0]),"+f"(d[1]),"+f"(d[2]),"+f"(d[3]) \
  : "r"(a[0]),"r"(a[1]),"r"(a[2]),"r"(a[3]), "r"(b[0]),"r"(b[1]))

#define LDSM4(r0,r1,r2,r3,addr) asm volatile( \
  "ldmatrix.sync.aligned.m8n8.x4.shared.b16 {%0,%1,%2,%3}, [%4];\n" \
  : "=r"(r0),"=r"(r1),"=r"(r2),"=r"(r3) : "r"(addr))

#define CPA(dst,src) asm volatile("cp.async.cg.shared.global [%0], [%1], 16;\n"::"r"(dst),"l"(src))
#define CPC()  asm volatile("cp.async.commit_group;\n")
#define CPW1() asm volatile("cp.async.wait_group 1;\n")
#define CPW0() asm volatile("cp.async.wait_group 0;\n")

__device__ __forceinline__ const hlf* act_base(int sel){
    switch(sel){
        case 0:  return g_xs;
        case 1:  return g_hsp;
        case 2:  return g_hdp;
        default: return g_V;
    }
}
__device__ __forceinline__ int rowmap(int m, int mode, int start, int lg){
    if (mode == 3) return m;
    int tree = m >> lg, pos = m & ((1<<lg)-1);
    if (mode == 0) return tree*NPT + start + pos;
    return tree*NPT + start + (pos>>1);   // mode 2: father
}

// smem (words), BK=64, AW=36 (32 data + 4 pad):
#define AW    36
#define A_ST  4608
#define B_OFF 9216
#define B_ST  4608
#define SMEMB ((B_OFF + 2*B_ST)*4)   // 73728 B
#define SP    132     // epilogue exchange row stride (words)

// ---------------- fused single-pass fp16 tensor-core GEMM ----------------
// 256 threads, 2 CTAs/SM. CTA tile 128 rows x 128 logical cols.
// 4x2 warp grid, 32x64 warp tiles, BK=64, double-buffered cp.async.
// epi: 0 leaf, 1 zr_bu, 2 zr_td, 3 th_bu, 4 th_td, 5 out
template<int NG>
__global__ __launch_bounds__(256,2)
void mma_g(int kend,
           int a0sel,int a0mode,int a0start,
           int a1sel,int a1mode,int a1start,
           int slot0,int slot1,
           const float* __restrict__ bias0, const float* __restrict__ bias1,
           int M, int lg, int epi, int e_sst, int e_fst,
           float* __restrict__ outp)
{
    extern __shared__ uint32_t smx[];
    uint32_t sb;
    asm("{ .reg .u64 t; cvta.to.shared.u64 t, %1; cvt.u32.u64 %0, t; }" : "=r"(sb) : "l"(smx));
    const int tid = threadIdx.x;
    const int m0 = blockIdx.y << 7;
    const int n0 = blockIdx.x * (NG==2 ? 64 : 128);

    // ---- loader setup: thread -> row (t>>1), 4 chunks of 8 halves ----
    const int row = tid >> 1;
    const int cb  = (tid & 1) * 4;

    const int am = min(m0 + row, M-1);
    const hlf* a0p = act_base(a0sel) + (size_t)rowmap(am,a0mode,a0start,lg)*HDIM;
    const hlf* a1p = a0p;
    const float* ch0 = nullptr; const float* ch1 = nullptr;
    if (kend > 512){
        if (a1mode == 1){
            int tree = am >> lg, pos = am & ((1<<lg)-1);
            int c0n = tree*NPT + a1start + (pos<<1);
            ch0 = g_h + (size_t)c0n*HDIM;
            ch1 = ch0 + HDIM;
        } else {
            a1p = act_base(a1sel) + (size_t)rowmap(am,a1mode,a1start,lg)*HDIM;
        }
    }
    // B: smem row <-> weight col
    int bslot, bcol;
    if (NG==2){ bslot = (row>=64)?slot1:slot0; bcol = n0 + (row&63); }
    else      { bslot = slot0;                 bcol = n0 + row; }
    const hlf* bptr = g_W + (size_t)bslot*524288 + (size_t)bcol*1024;

    float acc[2][8][4];
    #pragma unroll
    for (int a=0;a<2;a++)
      #pragma unroll
      for (int b=0;b<8;b++)
        #pragma unroll
        for (int c=0;c<4;c++) acc[a][b][c]=0.f;

    auto LOAD = [&](int s, int kt){
        if (kt < 512 || ch0 == nullptr){
            const hlf* ph = (kt<512)? a0p : a1p;
            int kl = kt & 511;
            #pragma unroll
            for (int j=0;j<4;j++){
                int c = cb+j;
                CPA(sb + (uint32_t)(s*A_ST + row*AW + c*4)*4, ph + kl + c*8);
            }
        } else {
            int kl = kt - 512;
            #pragma unroll
            for (int j=0;j<4;j++){
                int k = kl + (cb+j)*8;
                float4 x0 = *(const float4*)(ch0+k);
                float4 x1 = *(const float4*)(ch0+k+4);
                float4 y0 = *(const float4*)(ch1+k);
                float4 y1 = *(const float4*)(ch1+k+4);
                int idx = s*A_ST + row*AW + (cb+j)*4;
                smx[idx+0]=pack2f(x0.x+y0.x, x0.y+y0.y);
                smx[idx+1]=pack2f(x0.z+y0.z, x0.w+y0.w);
                smx[idx+2]=pack2f(x1.x+y1.x, x1.y+y1.y);
                smx[idx+3]=pack2f(x1.z+y1.z, x1.w+y1.w);
            }
        }
        #pragma unroll
        for (int j=0;j<4;j++){
            int c = cb+j;
            CPA(sb + (uint32_t)(B_OFF + s*B_ST + row*AW + c*4)*4, bptr + kt + c*8);
        }
    };

    const int L   = tid & 31;
    const int wid = tid >> 5;           // 0..7
    const int wm  = (wid >> 1) << 5;    // 0,32,64,96
    const int wn  = (wid &  1) << 6;    // 0,64 (logical cols)

    auto COMP = [&](int s){
        #pragma unroll
        for (int ks=0; ks<4; ks++){
            uint32_t af[2][4];
            #pragma unroll
            for (int mt=0;mt<2;mt++){
                uint32_t ad = sb + (uint32_t)(s*A_ST + (wm + mt*16 + (L&15))*AW)*4
                                 + ((L>>4)<<4) + (ks<<5);
                LDSM4(af[mt][0],af[mt][1],af[mt][2],af[mt][3], ad);
            }
            uint32_t bfr[8][2];
            #pragma unroll
            for (int tp=0;tp<4;tp++){
                int n = wn + tp*16 + (L&7) + ((L>>4)<<3);
                uint32_t bd = sb + (uint32_t)(B_OFF + s*B_ST + n*AW)*4
                                 + (((L>>3)&1)<<4) + (ks<<5);
                uint32_t r0,r1,r2,r3;
                LDSM4(r0,r1,r2,r3,bd);
                bfr[tp*2  ][0]=r0; bfr[tp*2  ][1]=r1;
                bfr[tp*2+1][0]=r2; bfr[tp*2+1][1]=r3;
            }
            #pragma unroll
            for (int mt=0;mt<2;mt++)
              #pragma unroll
              for (int nt=0;nt<8;nt++)
                  MMA_F16(acc[mt][nt], af[mt], bfr[nt]);
        }
    };

    const int niter = kend >> 6;
    LOAD(0,0); CPC();
    for (int it=0; it<niter; ++it){
        if (it+1 < niter){ LOAD((it+1)&1, (it+1)<<6); CPC(); CPW1(); }
        else             { CPW0(); }
        __syncthreads();
        COMP(it & 1);
        __syncthreads();
    }

    // ---------------- epilogue ----------------
    if (NG == 2){
        // stage 1: exchange pre-activations via smem
        float* Sf = reinterpret_cast<float*>(smx);
        #pragma unroll
        for (int mt=0;mt<2;mt++)
          #pragma unroll
          for (int e2=0;e2<2;e2++){
              int rl = wm + mt*16 + (L>>2) + e2*8;
              #pragma unroll
              for (int nt=0;nt<8;nt++){
                  int cl = wn + nt*8 + ((L&3)<<1);
                  Sf[rl*SP + cl]   = acc[mt][nt][e2*2];
                  Sf[rl*SP + cl+1] = acc[mt][nt][e2*2+1];
              }
          }
        __syncthreads();
        // stage 2: thread owns 1 row x 32 cols
        int rl = tid >> 1;
        int r = m0 + rl;
        if (r < M){
            int tree = r >> lg, pos = r & ((1<<lg)-1);
            int cg0 = (tid & 1) << 5;
            const float* Zr = Sf + rl*SP;
            int col0 = n0 + cg0;
            if (epi == 0){
                size_t o = (size_t)(tree*NPT + e_fst + pos)*HDIM + col0;
                #pragma unroll
                for (int q=0;q<32;q+=4){
                    float4 vz = *(const float4*)(Zr + cg0 + q);
                    float4 vt = *(const float4*)(Zr + 64 + cg0 + q);
                    float h0 = (1.f - sigf(vz.x))*tanhf(vt.x);
                    float h1 = (1.f - sigf(vz.y))*tanhf(vt.y);
                    float h2 = (1.f - sigf(vz.z))*tanhf(vt.z);
                    float h3 = (1.f - sigf(vz.w))*tanhf(vt.w);
                    *(float4*)(g_h + o + q) = make_float4(h0,h1,h2,h3);
                    st_h4(&g_hsp[o+q], h0,h1,h2,h3);
                }
            } else {   // epi 1 / 2
                size_t om = (size_t)r*HDIM + col0;
                size_t oc = (epi==1)
                    ? (size_t)(tree*NPT + e_sst + (pos<<1))*HDIM + col0
                    : (size_t)(tree*NPT + e_fst + (pos>>1))*HDIM + col0;
                #pragma unroll
                for (int q=0;q<32;q+=4){
                    float4 vz = *(const float4*)(Zr + cg0 + q);
                    float4 vr = *(const float4*)(Zr + 64 + cg0 + q);
                    float4 b0 = *(const float4*)(bias0 + col0 + q);
                    float4 b1 = *(const float4*)(bias1 + col0 + q);
                    float4 hs;
                    if (epi==1){
                        float4 c0 = *(const float4*)(g_h + oc + q);
                        float4 c1 = *(const float4*)(g_h + oc + HDIM + q);
                        hs = make_float4(c0.x+c1.x, c0.y+c1.y, c0.z+c1.z, c0.w+c1.w);
                    } else {
                        hs = *(const float4*)(g_hd + oc + q);
                    }
                    float4 zz = make_float4(sigf(vz.x+b0.x), sigf(vz.y+b0.y),
                                            sigf(vz.z+b0.z), sigf(vz.w+b0.w));
                    float r0 = sigf(vr.x+b1.x), r1 = sigf(vr.y+b1.y);
                    float r2 = sigf(vr.z+b1.z), r3 = sigf(vr.w+b1.w);
                    *(float4*)(g_z + om + q) = zz;
                    st_h4(&g_V[om+q], r0*hs.x, r1*hs.y, r2*hs.z, r3*hs.w);
                }
            }
        }
    } else {
        // NG==1: direct per-fragment epilogue (epi 3/4/5)
        #pragma unroll
        for (int mt=0;mt<2;mt++)
        #pragma unroll
        for (int e2=0;e2<2;e2++){
            int r = m0 + wm + mt*16 + (L>>2) + e2*8;
            if (r >= M) continue;
            int tree = r >> lg, pos = r & ((1<<lg)-1);
            #pragma unroll
            for (int nt=0;nt<8;nt++){
                int c = n0 + wn + nt*8 + ((L&3)<<1);
                float v0 = acc[mt][nt][e2*2+0];
                float v1 = acc[mt][nt][e2*2+1];
                if (epi == 5){
                    outp[(size_t)r*HDIM + c]   = v0 + bias0[c]   + bias1[c];
                    outp[(size_t)r*HDIM + c+1] = v1 + bias0[c+1] + bias1[c+1];
                } else {   // epi 3 / 4
                    float cand0 = tanhf(v0), cand1 = tanhf(v1);
                    size_t om = (size_t)r*HDIM + c;
                    float z0 = g_z[om], z1 = g_z[om+1];
                    float hs0, hs1; int node;
                    if (epi == 3){
                        size_t oc = (size_t)(tree*NPT + e_sst + (pos<<1))*HDIM + c;
                        hs0 = g_h[oc]   + g_h[oc+HDIM];
                        hs1 = g_h[oc+1] + g_h[oc+1+HDIM];
                        node = tree*NPT + e_fst + pos;
                    } else {
                        size_t of = (size_t)(tree*NPT + e_fst + (pos>>1))*HDIM + c;
                        hs0 = g_hd[of]; hs1 = g_hd[of+1];
                        node = tree*NPT + e_sst + pos;
                    }
                    float h0 = z0*hs0 + (1.f-z0)*cand0;
                    float h1 = z1*hs1 + (1.f-z1)*cand1;
                    size_t o = (size_t)node*HDIM + c;
                    if (epi == 3){
                        g_h[o]=h0; g_h[o+1]=h1;
                        st_h2(&g_hsp[o], h0, h1);
                    } else {
                        g_hd[o]=h0; g_hd[o+1]=h1;
                        st_h2(&g_hdp[o], h0, h1);
                    }
                }
            }
        }
    }
}

// ---------------- host orchestration ----------------
extern "C" void kernel_launch(void* const* d_in, const int* in_sizes, int n_in,
                              void* d_out, int out_size)
{
    (void)in_sizes; (void)n_in; (void)out_size;
    const float* feat = (const float*)d_in[0];
    const float* Wh   = (const float*)d_in[1];
    const float* Wz   = (const float*)d_in[2];
    const float* Wr   = (const float*)d_in[3];
    const float* Uh   = (const float*)d_in[4];
    const float* Uz   = (const float*)d_in[5];
    const float* bUz  = (const float*)d_in[6];
    const float* Ur   = (const float*)d_in[7];
    const float* bUr  = (const float*)d_in[8];
    const float* Whd  = (const float*)d_in[9];
    const float* Wzd  = (const float*)d_in[10];
    const float* Wrd  = (const float*)d_in[11];
    const float* Uhd  = (const float*)d_in[12];
    const float* Uzd  = (const float*)d_in[13];
    const float* bUzd = (const float*)d_in[14];
    const float* Urd  = (const float*)d_in[15];
    const float* bUrd = (const float*)d_in[16];
    const float* W1   = (const float*)d_in[17];
    const float* b1   = (const float*)d_in[18];
    const float* W2   = (const float*)d_in[19];
    const float* b2   = (const float*)d_in[20];
    float* out = (float*)d_out;

    cudaFuncSetAttribute(mma_g<1>, cudaFuncAttributeMaxDynamicSharedMemorySize, SMEMB);
    cudaFuncSetAttribute(mma_g<2>, cudaFuncAttributeMaxDynamicSharedMemorySize, SMEMB);

    // slots: 0 [Wz|Uz]  1 [Wr|Ur]  2 [Wh|Uh]  3 [Wzd|Uzd]  4 [Wrd|Urd]  5 [Whd|Uhd]  6 [W1|W2]
    split_w<<<dim3(2048,7),256>>>(Wz,Uz, Wr,Ur, Wh,Uh, Wzd,Uzd, Wrd,Urd, Whd,Uhd, W1,W2);
    split_feat<<<65520,256>>>(feat);

    static const int LS[12] = {0,2048,3072,3584,3840,3968,4032,4064,4080,4088,4092,4094};
    static const int LG[12] = {11,10,9,8,7,6,5,4,3,2,1,0};

    // ---- leaves: z = sig(X@Wz), th = X@Wh -> h ----
    mma_g<2><<<dim3(8,128),256,SMEMB>>>(512, 0,0,0, 0,0,0, 0,2,
                                        nullptr,nullptr, NB*2048, 11, 0, 0, 0, nullptr);

    // ---- bottom-up ----
    for (int l=0; l<11; l++){
        int lgf = LG[l+1];
        int M   = NB << lgf;
        int sst = LS[l], fst = LS[l+1];
        int mb  = (M+127)/128;
        // z,r: [X_fa | sum(children h)] @ [Wz;Uz],[Wr;Ur]
        mma_g<2><<<dim3(8,mb),256,SMEMB>>>(1024, 0,0,fst, 0,1,sst, 0,1,
                                           bUz,bUr, M, lgf, 1, sst, fst, nullptr);
        // th: [X_fa | V] @ [Wh;Uh] -> h
        mma_g<1><<<dim3(4,mb),256,SMEMB>>>(1024, 0,0,fst, 3,3,0, 2,2,
                                           nullptr,nullptr, M, lgf, 3, sst, fst, nullptr);
    }

    root_copy<<<16,256>>>();

    // ---- top-down ----
    for (int l=10; l>=0; l--){
        int lgs = LG[l];
        int M   = NB << lgs;
        int sst = LS[l], fst = LS[l+1];
        int mb  = (M+127)/128;
        // zd,rd: [X_son | hd_father] @ [Wzd;Uzd],[Wrd;Urd]
        mma_g<2><<<dim3(8,mb),256,SMEMB>>>(1024, 0,0,sst, 2,2,fst, 3,4,
                                           bUzd,bUrd, M, lgs, 2, sst, fst, nullptr);
        // th: [X_son | V] @ [Whd;Uhd] -> hd
        mma_g<1><<<dim3(4,mb),256,SMEMB>>>(1024, 0,0,sst, 3,3,0, 5,5,
                                           nullptr,nullptr, M, lgs, 4, sst, fst, nullptr);
    }

    // ---- output: [h|hd] @ [W1;W2] + b1 + b2 ----
    mma_g<1><<<dim3(4,256),256,SMEMB>>>(1024, 1,3,0, 2,3,0, 6,6,
                                        b1,b2, NTOT, 1, 5, 0, 0, out);
}

// round 10
// speedup vs baseline: 1.1590x; 1.1590x over previous
#include <cuda_runtime.h>
#include <cuda_fp16.h>
#include <math.h>
#include <stdint.h>

#define HDIM 512
#define NPT  4095
#define NB   8
#define NTOT (NPT*NB)

typedef __half hlf;

// ---------------- device scratch ----------------
__device__ float g_h [(size_t)NTOT*HDIM];
__device__ float g_hd[(size_t)NTOT*HDIM];
__device__ float g_z [(size_t)16384*HDIM];
__device__ hlf g_xs [(size_t)NTOT*HDIM];
__device__ hlf g_hsp[(size_t)NTOT*HDIM];
__device__ hlf g_hdp[(size_t)NTOT*HDIM];
__device__ hlf g_V  [(size_t)16384*HDIM];
__device__ hlf g_W  [(size_t)7*512*1024];

__device__ __forceinline__ float sigf(float x){ return 1.f/(1.f+expf(-x)); }
__device__ __forceinline__ uint32_t pack2f(float a, float b){
    __half2 p = __floats2half2_rn(a,b);
    return *reinterpret_cast<uint32_t*>(&p);
}
__device__ __forceinline__ void st_h2(hlf* p, float a, float b){
    *reinterpret_cast<__half2*>(p) = __floats2half2_rn(a,b);
}
__device__ __forceinline__ void st_h4(hlf* p, float a, float b, float c, float d){
    uint2 v; v.x = pack2f(a,b); v.y = pack2f(c,d);
    *reinterpret_cast<uint2*>(p) = v;
}

// ---------------- setup kernels ----------------
__global__ void split_w(const float* Wz,const float* Uz,const float* Wr,const float* Ur,
                        const float* Wh,const float* Uh,const float* Wzd,const float* Uzd,
                        const float* Wrd,const float* Urd,const float* Whd,const float* Uhd,
                        const float* W1,const float* W2)
{
    int slot = blockIdx.y;
    const float* Wp; const float* Up;
    switch(slot){
        case 0: Wp=Wz;  Up=Uz;  break;
        case 1: Wp=Wr;  Up=Ur;  break;
        case 2: Wp=Wh;  Up=Uh;  break;
        case 3: Wp=Wzd; Up=Uzd; break;
        case 4: Wp=Wrd; Up=Urd; break;
        case 5: Wp=Whd; Up=Uhd; break;
        default:Wp=W1;  Up=W2;  break;
    }
    int idx = blockIdx.x*256 + threadIdx.x;
    int n = idx >> 10, k = idx & 1023;
    float x = (k < 512) ? Wp[n*512 + k] : Up[n*512 + (k-512)];
    g_W[(size_t)slot*524288 + idx] = __float2half_rn(x);
}

__global__ void split_feat(const float* __restrict__ src)
{
    size_t idx = (size_t)blockIdx.x*256 + threadIdx.x;
    g_xs[idx] = __float2half_rn(src[idx]);
}

__global__ void root_copy()
{
    int idx = blockIdx.x*256 + threadIdx.x;
    if (idx >= NB*HDIM) return;
    int tree = idx >> 9, k = idx & 511;
    size_t o = (size_t)(tree*NPT + NPT-1)*HDIM + k;
    float v = g_h[o];
    g_hd[o] = v;
    g_hdp[o] = __float2half_rn(v);
}

// ---------------- PTX helpers ----------------
#define MMA_F16(d, a, b) asm volatile( \
  "mma.sync.aligned.m16n8k16.row.col.f32.f16.f16.f32 " \
  "{%0,%1,%2,%3}, {%4,%5,%6,%7}, {%8,%9}, {%0,%1,%2,%3};\n" \
  : "+f"(d[0]),"+f"(d[1]),"+f"(d[2]),"+f"(d[3]) \
  : "r"(a[0]),"r"(a[1]),"r"(a[2]),"r"(a[3]), "r"(b[0]),"r"(b[1]))

#define LDSM4(r0,r1,r2,r3,addr) asm volatile( \
  "ldmatrix.sync.aligned.m8n8.x4.shared.b16 {%0,%1,%2,%3}, [%4];\n" \
  : "=r"(r0),"=r"(r1),"=r"(r2),"=r"(r3) : "r"(addr))

#define CPA(dst,src) asm volatile("cp.async.cg.shared.global [%0], [%1], 16;\n"::"r"(dst),"l"(src))
#define CPC()  asm volatile("cp.async.commit_group;\n")
#define CPW1() asm volatile("cp.async.wait_group 1;\n")
#define CPW0() asm volatile("cp.async.wait_group 0;\n")

__device__ __forceinline__ const hlf* act_base(int sel){
    switch(sel){
        case 0:  return g_xs;
        case 1:  return g_hsp;
        case 2:  return g_hdp;
        default: return g_V;
    }
}
__device__ __forceinline__ int rowmap(int m, int mode, int start, int lg){
    if (mode == 3) return m;
    int tree = m >> lg, pos = m & ((1<<lg)-1);
    if (mode == 0) return tree*NPT + start + pos;
    return tree*NPT + start + (pos>>1);   // mode 2: father
}

// smem (words), BK=64, AW=36 (32 data + 4 pad), 3 stages:
//   A: 3 x 4608 w   B: 3 x 4608 w starting at 13824
#define AW    36
#define A_ST  4608
#define B_OFF 13824
#define B_ST  4608
#define SMEMB ((B_OFF + 3*B_ST)*4)   // 110592 B
#define SP    132     // epilogue exchange row stride (words)

// ---------------- fused single-pass fp16 tensor-core GEMM ----------------
// 512 threads, CTA tile 128 rows x 128 logical cols (NG=2: 64 x {g0,g1}; NG=1: 128).
// 4x4 warp grid, 32x32 warp tiles, BK=64, 3-stage cp.async, ONE barrier/iter.
// epi: 0 leaf, 1 zr_bu, 2 zr_td, 3 th_bu, 4 th_td, 5 out
template<int NG>
__global__ __launch_bounds__(512,1)
void mma_g(int kend,
           int a0sel,int a0mode,int a0start,
           int a1sel,int a1mode,int a1start,
           int slot0,int slot1,
           const float* __restrict__ bias0, const float* __restrict__ bias1,
           int M, int lg, int epi, int e_sst, int e_fst,
           float* __restrict__ outp)
{
    extern __shared__ uint32_t smx[];
    uint32_t sb;
    asm("{ .reg .u64 t; cvta.to.shared.u64 t, %1; cvt.u32.u64 %0, t; }" : "=r"(sb) : "l"(smx));
    const int tid = threadIdx.x;
    const int m0 = blockIdx.y << 7;
    const int n0 = blockIdx.x * (NG==2 ? 64 : 128);

    // ---- loader setup: thread -> row (t>>2), 2 chunks of 8 halves ----
    const int row = tid >> 2;
    const int cb  = (tid & 3) * 2;

    const int am = min(m0 + row, M-1);
    const hlf* a0p = act_base(a0sel) + (size_t)rowmap(am,a0mode,a0start,lg)*HDIM;
    const hlf* a1p = a0p;
    const float* ch0 = nullptr; const float* ch1 = nullptr;
    if (kend > 512){
        if (a1mode == 1){
            int tree = am >> lg, pos = am & ((1<<lg)-1);
            int c0n = tree*NPT + a1start + (pos<<1);
            ch0 = g_h + (size_t)c0n*HDIM;
            ch1 = ch0 + HDIM;
        } else {
            a1p = act_base(a1sel) + (size_t)rowmap(am,a1mode,a1start,lg)*HDIM;
        }
    }
    // B: smem row <-> weight col
    int bslot, bcol;
    if (NG==2){ bslot = (row>=64)?slot1:slot0; bcol = n0 + (row&63); }
    else      { bslot = slot0;                 bcol = n0 + row; }
    const hlf* bptr = g_W + (size_t)bslot*524288 + (size_t)bcol*1024;

    float acc[2][4][4];
    #pragma unroll
    for (int a=0;a<2;a++)
      #pragma unroll
      for (int b=0;b<4;b++)
        #pragma unroll
        for (int c=0;c<4;c++) acc[a][b][c]=0.f;

    auto LOAD = [&](int s, int kt){
        if (kt < 512 || ch0 == nullptr){
            const hlf* ph = (kt<512)? a0p : a1p;
            int kl = kt & 511;
            #pragma unroll
            for (int j=0;j<2;j++){
                int c = cb+j;
                CPA(sb + (uint32_t)(s*A_ST + row*AW + c*4)*4, ph + kl + c*8);
            }
        } else {
            int kl = kt - 512;
            #pragma unroll
            for (int j=0;j<2;j++){
                int k = kl + (cb+j)*8;
                float4 x0 = *(const float4*)(ch0+k);
                float4 x1 = *(const float4*)(ch0+k+4);
                float4 y0 = *(const float4*)(ch1+k);
                float4 y1 = *(const float4*)(ch1+k+4);
                int idx = s*A_ST + row*AW + (cb+j)*4;
                smx[idx+0]=pack2f(x0.x+y0.x, x0.y+y0.y);
                smx[idx+1]=pack2f(x0.z+y0.z, x0.w+y0.w);
                smx[idx+2]=pack2f(x1.x+y1.x, x1.y+y1.y);
                smx[idx+3]=pack2f(x1.z+y1.z, x1.w+y1.w);
            }
        }
        #pragma unroll
        for (int j=0;j<2;j++){
            int c = cb+j;
            CPA(sb + (uint32_t)(B_OFF + s*B_ST + row*AW + c*4)*4, bptr + kt + c*8);
        }
    };

    const int L   = tid & 31;
    const int wid = tid >> 5;
    const int wm  = (wid >> 2) << 5;   // 0,32,64,96
    const int wn  = (wid &  3) << 5;   // 0,32,64,96 (logical cols)

    auto COMP = [&](int s){
        #pragma unroll
        for (int ks=0; ks<4; ks++){
            uint32_t af[2][4];
            #pragma unroll
            for (int mt=0;mt<2;mt++){
                uint32_t ad = sb + (uint32_t)(s*A_ST + (wm + mt*16 + (L&15))*AW)*4
                                 + ((L>>4)<<4) + (ks<<5);
                LDSM4(af[mt][0],af[mt][1],af[mt][2],af[mt][3], ad);
            }
            uint32_t bfr[4][2];
            #pragma unroll
            for (int tp=0;tp<2;tp++){
                int n = wn + tp*16 + (L&7) + ((L>>4)<<3);
                uint32_t bd = sb + (uint32_t)(B_OFF + s*B_ST + n*AW)*4
                                 + (((L>>3)&1)<<4) + (ks<<5);
                uint32_t r0,r1,r2,r3;
                LDSM4(r0,r1,r2,r3,bd);
                bfr[tp*2  ][0]=r0; bfr[tp*2  ][1]=r1;
                bfr[tp*2+1][0]=r2; bfr[tp*2+1][1]=r3;
            }
            #pragma unroll
            for (int mt=0;mt<2;mt++)
              #pragma unroll
              for (int nt=0;nt<4;nt++)
                  MMA_F16(acc[mt][nt], af[mt], bfr[nt]);
        }
    };

    // ---- 3-stage multistage mainloop: ONE barrier per iteration ----
    const int niter = kend >> 6;   // >= 8 always
    LOAD(0, 0);  CPC();
    LOAD(1, 64); CPC();
    for (int it=0; it<niter; ++it){
        if (it == niter-1) { CPW0(); } else { CPW1(); }
        __syncthreads();
        int pf = it + 2;
        if (pf < niter){
            int s = pf % 3;
            LOAD(s, pf << 6); CPC();
        }
        COMP(it % 3);
    }
    __syncthreads();   // smem reuse in epilogue

    // ---------------- epilogue ----------------
    if (NG == 2){
        // stage 1: exchange pre-activations via smem
        float* Sf = reinterpret_cast<float*>(smx);
        #pragma unroll
        for (int mt=0;mt<2;mt++)
          #pragma unroll
          for (int e2=0;e2<2;e2++){
              int rl = wm + mt*16 + (L>>2) + e2*8;
              #pragma unroll
              for (int nt=0;nt<4;nt++){
                  int cl = wn + nt*8 + ((L&3)<<1);
                  Sf[rl*SP + cl]   = acc[mt][nt][e2*2];
                  Sf[rl*SP + cl+1] = acc[mt][nt][e2*2+1];
              }
          }
        __syncthreads();
        // stage 2: thread owns 1 row x 16 cols
        int rl = tid >> 2;
        int r = m0 + rl;
        if (r < M){
            int tree = r >> lg, pos = r & ((1<<lg)-1);
            int cg0 = (tid & 3) << 4;
            const float* Zr = Sf + rl*SP;
            int col0 = n0 + cg0;
            if (epi == 0){
                size_t o = (size_t)(tree*NPT + e_fst + pos)*HDIM + col0;
                #pragma unroll
                for (int q=0;q<16;q+=4){
                    float4 vz = *(const float4*)(Zr + cg0 + q);
                    float4 vt = *(const float4*)(Zr + 64 + cg0 + q);
                    float h0 = (1.f - sigf(vz.x))*tanhf(vt.x);
                    float h1 = (1.f - sigf(vz.y))*tanhf(vt.y);
                    float h2 = (1.f - sigf(vz.z))*tanhf(vt.z);
                    float h3 = (1.f - sigf(vz.w))*tanhf(vt.w);
                    *(float4*)(g_h + o + q) = make_float4(h0,h1,h2,h3);
                    st_h4(&g_hsp[o+q], h0,h1,h2,h3);
                }
            } else {   // epi 1 / 2
                size_t om = (size_t)r*HDIM + col0;
                size_t oc = (epi==1)
                    ? (size_t)(tree*NPT + e_sst + (pos<<1))*HDIM + col0
                    : (size_t)(tree*NPT + e_fst + (pos>>1))*HDIM + col0;
                #pragma unroll
                for (int q=0;q<16;q+=4){
                    float4 vz = *(const float4*)(Zr + cg0 + q);
                    float4 vr = *(const float4*)(Zr + 64 + cg0 + q);
                    float4 b0 = *(const float4*)(bias0 + col0 + q);
                    float4 b1 = *(const float4*)(bias1 + col0 + q);
                    float4 hs;
                    if (epi==1){
                        float4 c0 = *(const float4*)(g_h + oc + q);
                        float4 c1 = *(const float4*)(g_h + oc + HDIM + q);
                        hs = make_float4(c0.x+c1.x, c0.y+c1.y, c0.z+c1.z, c0.w+c1.w);
                    } else {
                        hs = *(const float4*)(g_hd + oc + q);
                    }
                    float4 zz = make_float4(sigf(vz.x+b0.x), sigf(vz.y+b0.y),
                                            sigf(vz.z+b0.z), sigf(vz.w+b0.w));
                    float r0 = sigf(vr.x+b1.x), r1 = sigf(vr.y+b1.y);
                    float r2 = sigf(vr.z+b1.z), r3 = sigf(vr.w+b1.w);
                    *(float4*)(g_z + om + q) = zz;
                    st_h4(&g_V[om+q], r0*hs.x, r1*hs.y, r2*hs.z, r3*hs.w);
                }
            }
        }
    } else {
        // NG==1: direct per-fragment epilogue (epi 3/4/5)
        #pragma unroll
        for (int mt=0;mt<2;mt++)
        #pragma unroll
        for (int e2=0;e2<2;e2++){
            int r = m0 + wm + mt*16 + (L>>2) + e2*8;
            if (r >= M) continue;
            int tree = r >> lg, pos = r & ((1<<lg)-1);
            #pragma unroll
            for (int nt=0;nt<4;nt++){
                int c = n0 + wn + nt*8 + ((L&3)<<1);
                float v0 = acc[mt][nt][e2*2+0];
                float v1 = acc[mt][nt][e2*2+1];
                if (epi == 5){
                    outp[(size_t)r*HDIM + c]   = v0 + bias0[c]   + bias1[c];
                    outp[(size_t)r*HDIM + c+1] = v1 + bias0[c+1] + bias1[c+1];
                } else {   // epi 3 / 4
                    float cand0 = tanhf(v0), cand1 = tanhf(v1);
                    size_t om = (size_t)r*HDIM + c;
                    float z0 = g_z[om], z1 = g_z[om+1];
                    float hs0, hs1; int node;
                    if (epi == 3){
                        size_t oc = (size_t)(tree*NPT + e_sst + (pos<<1))*HDIM + c;
                        hs0 = g_h[oc]   + g_h[oc+HDIM];
                        hs1 = g_h[oc+1] + g_h[oc+1+HDIM];
                        node = tree*NPT + e_fst + pos;
                    } else {
                        size_t of = (size_t)(tree*NPT + e_fst + (pos>>1))*HDIM + c;
                        hs0 = g_hd[of]; hs1 = g_hd[of+1];
                        node = tree*NPT + e_sst + pos;
                    }
                    float h0 = z0*hs0 + (1.f-z0)*cand0;
                    float h1 = z1*hs1 + (1.f-z1)*cand1;
                    size_t o = (size_t)node*HDIM + c;
                    if (epi == 3){
                        g_h[o]=h0; g_h[o+1]=h1;
                        st_h2(&g_hsp[o], h0, h1);
                    } else {
                        g_hd[o]=h0; g_hd[o+1]=h1;
                        st_h2(&g_hdp[o], h0, h1);
                    }
                }
            }
        }
    }
}

// ---------------- host orchestration ----------------
extern "C" void kernel_launch(void* const* d_in, const int* in_sizes, int n_in,
                              void* d_out, int out_size)
{
    (void)in_sizes; (void)n_in; (void)out_size;
    const float* feat = (const float*)d_in[0];
    const float* Wh   = (const float*)d_in[1];
    const float* Wz   = (const float*)d_in[2];
    const float* Wr   = (const float*)d_in[3];
    const float* Uh   = (const float*)d_in[4];
    const float* Uz   = (const float*)d_in[5];
    const float* bUz  = (const float*)d_in[6];
    const float* Ur   = (const float*)d_in[7];
    const float* bUr  = (const float*)d_in[8];
    const float* Whd  = (const float*)d_in[9];
    const float* Wzd  = (const float*)d_in[10];
    const float* Wrd  = (const float*)d_in[11];
    const float* Uhd  = (const float*)d_in[12];
    const float* Uzd  = (const float*)d_in[13];
    const float* bUzd = (const float*)d_in[14];
    const float* Urd  = (const float*)d_in[15];
    const float* bUrd = (const float*)d_in[16];
    const float* W1   = (const float*)d_in[17];
    const float* b1   = (const float*)d_in[18];
    const float* W2   = (const float*)d_in[19];
    const float* b2   = (const float*)d_in[20];
    float* out = (float*)d_out;

    cudaFuncSetAttribute(mma_g<1>, cudaFuncAttributeMaxDynamicSharedMemorySize, SMEMB);
    cudaFuncSetAttribute(mma_g<2>, cudaFuncAttributeMaxDynamicSharedMemorySize, SMEMB);

    // slots: 0 [Wz|Uz]  1 [Wr|Ur]  2 [Wh|Uh]  3 [Wzd|Uzd]  4 [Wrd|Urd]  5 [Whd|Uhd]  6 [W1|W2]
    split_w<<<dim3(2048,7),256>>>(Wz,Uz, Wr,Ur, Wh,Uh, Wzd,Uzd, Wrd,Urd, Whd,Uhd, W1,W2);
    split_feat<<<65520,256>>>(feat);

    static const int LS[12] = {0,2048,3072,3584,3840,3968,4032,4064,4080,4088,4092,4094};
    static const int LG[12] = {11,10,9,8,7,6,5,4,3,2,1,0};

    // ---- leaves: z = sig(X@Wz), th = X@Wh -> h ----
    mma_g<2><<<dim3(8,128),512,SMEMB>>>(512, 0,0,0, 0,0,0, 0,2,
                                        nullptr,nullptr, NB*2048, 11, 0, 0, 0, nullptr);

    // ---- bottom-up ----
    for (int l=0; l<11; l++){
        int lgf = LG[l+1];
        int M   = NB << lgf;
        int sst = LS[l], fst = LS[l+1];
        int mb  = (M+127)/128;
        // z,r: [X_fa | sum(children h)] @ [Wz;Uz],[Wr;Ur]
        mma_g<2><<<dim3(8,mb),512,SMEMB>>>(1024, 0,0,fst, 0,1,sst, 0,1,
                                           bUz,bUr, M, lgf, 1, sst, fst, nullptr);
        // th: [X_fa | V] @ [Wh;Uh] -> h
        mma_g<1><<<dim3(4,mb),512,SMEMB>>>(1024, 0,0,fst, 3,3,0, 2,2,
                                           nullptr,nullptr, M, lgf, 3, sst, fst, nullptr);
    }

    root_copy<<<16,256>>>();

    // ---- top-down ----
    for (int l=10; l>=0; l--){
        int lgs = LG[l];
        int M   = NB << lgs;
        int sst = LS[l], fst = LS[l+1];
        int mb  = (M+127)/128;
        // zd,rd: [X_son | hd_father] @ [Wzd;Uzd],[Wrd;Urd]
        mma_g<2><<<dim3(8,mb),512,SMEMB>>>(1024, 0,0,sst, 2,2,fst, 3,4,
                                           bUzd,bUrd, M, lgs, 2, sst, fst, nullptr);
        // th: [X_son | V] @ [Whd;Uhd] -> hd
        mma_g<1><<<dim3(4,mb),512,SMEMB>>>(1024, 0,0,sst, 3,3,0, 5,5,
                                           nullptr,nullptr, M, lgs, 4, sst, fst, nullptr);
    }

    // ---- output: [h|hd] @ [W1;W2] + b1 + b2 ----
    mma_g<1><<<dim3(4,256),512,SMEMB>>>(1024, 1,3,0, 2,3,0, 6,6,
                                        b1,b2, NTOT, 1, 5, 0, 0, out);
}